// round 9
// baseline (speedup 1.0000x reference)
#include <cuda_runtime.h>
#include <cuda_bf16.h>
#include <cstdint>

// Sparse 3x3x3 conv block, 2 layers, N=64, D=128.
// Center tap (offset 13) computed densely (no gather list, no atomics, bias
// fused, STG stores). 26 neighbor taps via compacted tile table + persistent
// strided blocks, FFMA2 (fma.rn.f32x2) inner loop, red.global.add.v4.f32
// scatter. Layer-1 ReLU fused into layer-2 gathers.
// NOTE: no min-blocks launch_bounds clause — a reg cap of 128 forces inner
// loop spills (measured 6.5x regression in R8).

#define DG   128
#define NCH  64
#define MAXM 131072
#define NOFF 27
#define CENTER 13
#define MAXTILES (26 * 1024 + 64)

__device__ __align__(16) int   g_lookup[DG * DG * DG];
__device__ __align__(16) int   g_cnt[NOFF];
__device__ __align__(16) int   g_pout[NOFF * MAXM];
__device__ __align__(16) int   g_pin [NOFF * MAXM];
__device__ __align__(16) float g_h   [MAXM * NCH];
__device__ __align__(16) int   g_tiletab[MAXTILES];
__device__ int g_ntiles;

// ---------------------------------------------------------------------------
__global__ void k_fill(int nquad) {
    int i = blockIdx.x * blockDim.x + threadIdx.x;
    if (i < nquad) ((int4*)g_lookup)[i] = make_int4(-1, -1, -1, -1);
    if (i < NOFF)  g_cnt[i] = 0;
}

__global__ void k_scatter(const int* __restrict__ coords, int M) {
    int i = blockIdx.x * blockDim.x + threadIdx.x;
    if (i >= M) return;
    int x = coords[3 * i + 0];
    int y = coords[3 * i + 1];
    int z = coords[3 * i + 2];
    g_lookup[(x * DG + y) * DG + z] = i;
}

// Pair lists for the 26 non-center offsets (warp-aggregated append).
__global__ void k_pairs(const int* __restrict__ coords, int M) {
    int i    = blockIdx.x * blockDim.x + threadIdx.x;
    int lane = threadIdx.x & 31;
    bool act = (i < M) && (i < MAXM);
    int cx = 0, cy = 0, cz = 0;
    if (act) {
        cx = coords[3 * i + 0];
        cy = coords[3 * i + 1];
        cz = coords[3 * i + 2];
    }
    for (int k = 0; k < NOFF; k++) {
        if (k == CENTER) continue;
        int dx = k / 9 - 1, dy = (k / 3) % 3 - 1, dz = k % 3 - 1;
        int nidx = -1;
        if (act) {
            int nx = cx + dx, ny = cy + dy, nz = cz + dz;
            if (nx >= 0 && nx < DG && ny >= 0 && ny < DG && nz >= 0 && nz < DG)
                nidx = g_lookup[(nx * DG + ny) * DG + nz];
        }
        bool valid = (nidx >= 0);
        unsigned m = __ballot_sync(0xffffffffu, valid);
        if (!m) continue;
        int total  = __popc(m);
        int leader = __ffs(m) - 1;
        int base = 0;
        if (lane == leader) base = atomicAdd(&g_cnt[k], total);
        base = __shfl_sync(0xffffffffu, base, leader);
        if (valid) {
            int pos = k * MAXM + base + __popc(m & ((1u << lane) - 1));
            g_pout[pos] = i;
            g_pin [pos] = nidx;
        }
    }
}

// Compact (offset, tile) descriptors: desc = (k<<16)|t. One block.
__global__ void k_tilesbuild() {
    __shared__ int pref[NOFF];
    int tid = threadIdx.x;
    if (tid == 0) {
        int s = 0;
        for (int k = 0; k < NOFF; k++) {
            pref[k] = s;
            if (k != CENTER) s += (g_cnt[k] + 127) / 128;
        }
        g_ntiles = s;
    }
    __syncthreads();
    for (int k = 0; k < NOFF; k++) {
        if (k == CENTER) continue;
        int nt = (g_cnt[k] + 127) / 128;
        for (int t = tid; t < nt; t += blockDim.x)
            g_tiletab[pref[k] + t] = (k << 16) | t;
    }
}

__global__ void k_relu4(float4* __restrict__ x, int nquad) {
    int i = blockIdx.x * blockDim.x + threadIdx.x;
    if (i < nquad) {
        float4 v = x[i];
        v.x = fmaxf(v.x, 0.f); v.y = fmaxf(v.y, 0.f);
        v.z = fmaxf(v.z, 0.f); v.w = fmaxf(v.w, 0.f);
        x[i] = v;
    }
}

// ---------------------------------------------------------------------------
__device__ __forceinline__ void fma2(unsigned long long& d,
                                     unsigned long long a,
                                     unsigned long long b) {
    asm("fma.rn.f32x2 %0, %1, %2, %3;" : "=l"(d) : "l"(a), "l"(b), "l"(d));
}
__device__ __forceinline__ unsigned long long dup2(float s) {
    unsigned long long d;
    unsigned u = __float_as_uint(s);
    asm("mov.b64 %0, {%1, %1};" : "=l"(d) : "r"(u));
    return d;
}
__device__ __forceinline__ float lo32(unsigned long long v) {
    return __uint_as_float((unsigned)v);
}
__device__ __forceinline__ float hi32(unsigned long long v) {
    return __uint_as_float((unsigned)(v >> 32));
}
__device__ __forceinline__ void red4(float* p, float a, float b, float c, float d) {
    asm volatile("red.global.add.v4.f32 [%0], {%1, %2, %3, %4};"
                 :: "l"(p), "f"(a), "f"(b), "f"(c), "f"(d) : "memory");
}

// Shared FFMA2 mainloop over sGT[j][p] x sW[j][c]: 8 points x 8 channels
// (4 packed channel-pairs) per thread.
__device__ __forceinline__ void gemm_tile(const float* sGT, const float* sW,
                                          int pg, int cg,
                                          unsigned long long (&acc)[8][4]) {
#pragma unroll
    for (int a = 0; a < 8; a++)
#pragma unroll
        for (int b = 0; b < 4; b++) acc[a][b] = 0ull;
    const float* gtb = sGT + pg * 8;
    const float* wb  = sW  + cg * 8;
#pragma unroll 4
    for (int j = 0; j < NCH; j++) {
        float4 a0 = *(const float4*)(gtb + j * 128);
        float4 a1 = *(const float4*)(gtb + j * 128 + 4);
        unsigned long long av[8];
        av[0] = dup2(a0.x); av[1] = dup2(a0.y);
        av[2] = dup2(a0.z); av[3] = dup2(a0.w);
        av[4] = dup2(a1.x); av[5] = dup2(a1.y);
        av[6] = dup2(a1.z); av[7] = dup2(a1.w);
        ulonglong2 b01 = *(const ulonglong2*)(wb + j * 64);
        ulonglong2 b23 = *(const ulonglong2*)(wb + j * 64 + 4);
        unsigned long long bv[4] = {b01.x, b01.y, b23.x, b23.y};
#pragma unroll
        for (int pp = 0; pp < 8; pp++)
#pragma unroll
            for (int c2 = 0; c2 < 4; c2++)
                fma2(acc[pp][c2], av[pp], bv[c2]);
    }
}

// Center tap: out[i] = bias + x[i] @ Wc, dense over points, STG stores.
template<bool RELU>
__global__ void __launch_bounds__(128) k_center(const float* __restrict__ x,
                                                const float* __restrict__ Wc,
                                                const float* __restrict__ bias,
                                                float* __restrict__ out, int M) {
    extern __shared__ float sm[];
    float* sW  = sm;
    float* sGT = sm + 4096;

    int base = blockIdx.x * 128;
    int tx = threadIdx.x;

    const float4* Wk4 = (const float4*)Wc;
    float4* sW4 = (float4*)sW;
#pragma unroll
    for (int t = 0; t < 8; t++) sW4[tx + t * 128] = Wk4[tx + t * 128];

    int p = tx;
    int row = base + p;
    if (row < M) {
        const float4* r4 = (const float4*)(x + (size_t)row * NCH);
#pragma unroll
        for (int q = 0; q < 16; q++) {
            float4 v = r4[q];
            if (RELU) {
                v.x = fmaxf(v.x, 0.f); v.y = fmaxf(v.y, 0.f);
                v.z = fmaxf(v.z, 0.f); v.w = fmaxf(v.w, 0.f);
            }
            sGT[(4 * q + 0) * 128 + p] = v.x;
            sGT[(4 * q + 1) * 128 + p] = v.y;
            sGT[(4 * q + 2) * 128 + p] = v.z;
            sGT[(4 * q + 3) * 128 + p] = v.w;
        }
    } else {
#pragma unroll
        for (int j = 0; j < NCH; j++) sGT[j * 128 + p] = 0.0f;
    }
    __syncthreads();

    int cg = tx & 7, pg = tx >> 3;
    unsigned long long acc[8][4];
    gemm_tile(sGT, sW, pg, cg, acc);

    float4 bA = *(const float4*)(bias + cg * 8);
    float4 bB = *(const float4*)(bias + cg * 8 + 4);
#pragma unroll
    for (int pp = 0; pp < 8; pp++) {
        int r = base + pg * 8 + pp;
        if (r < M) {
            float* o = out + (size_t)r * NCH + cg * 8;
            float4 v0 = make_float4(lo32(acc[pp][0]) + bA.x, hi32(acc[pp][0]) + bA.y,
                                    lo32(acc[pp][1]) + bA.z, hi32(acc[pp][1]) + bA.w);
            float4 v1 = make_float4(lo32(acc[pp][2]) + bB.x, hi32(acc[pp][2]) + bB.y,
                                    lo32(acc[pp][3]) + bB.z, hi32(acc[pp][3]) + bB.w);
            *(float4*)o = v0;
            *(float4*)(o + 4) = v1;
        }
    }
}

// 26 neighbor taps: persistent blocks stride over the compact tile table.
template<bool RELU>
__global__ void __launch_bounds__(128) k_off(const float* __restrict__ x,
                                             const float* __restrict__ W,
                                             float* __restrict__ out) {
    extern __shared__ float sm[];
    float* sW  = sm;
    float* sGT = sm + 4096;
    int tx = threadIdx.x;
    int ntiles = g_ntiles;

    for (int ti = blockIdx.x; ti < ntiles; ti += gridDim.x) {
        __syncthreads();   // protect smem from previous iteration's readers
        int desc = g_tiletab[ti];
        int k    = desc >> 16;
        int base = (desc & 0xffff) * 128;
        int cnt  = g_cnt[k];

        const float4* Wk4 = (const float4*)(W + k * (NCH * NCH));
        float4* sW4 = (float4*)sW;
#pragma unroll
        for (int t = 0; t < 8; t++) sW4[tx + t * 128] = Wk4[tx + t * 128];

        int p = tx;
        if (base + p < cnt) {
            int gidx = g_pin[k * MAXM + base + p];
            const float4* r4 = (const float4*)(x + (size_t)gidx * NCH);
#pragma unroll
            for (int q = 0; q < 16; q++) {
                float4 v = r4[q];
                if (RELU) {
                    v.x = fmaxf(v.x, 0.f); v.y = fmaxf(v.y, 0.f);
                    v.z = fmaxf(v.z, 0.f); v.w = fmaxf(v.w, 0.f);
                }
                sGT[(4 * q + 0) * 128 + p] = v.x;
                sGT[(4 * q + 1) * 128 + p] = v.y;
                sGT[(4 * q + 2) * 128 + p] = v.z;
                sGT[(4 * q + 3) * 128 + p] = v.w;
            }
        } else {
#pragma unroll
            for (int j = 0; j < NCH; j++) sGT[j * 128 + p] = 0.0f;
        }
        __syncthreads();

        int cg = tx & 7, pg = tx >> 3;
        unsigned long long acc[8][4];
        gemm_tile(sGT, sW, pg, cg, acc);

#pragma unroll
        for (int pp = 0; pp < 8; pp++) {
            int pairidx = base + pg * 8 + pp;
            if (pairidx < cnt) {
                int row = g_pout[k * MAXM + pairidx];
                float* o = out + (size_t)row * NCH + cg * 8;
                red4(o,     lo32(acc[pp][0]), hi32(acc[pp][0]),
                            lo32(acc[pp][1]), hi32(acc[pp][1]));
                red4(o + 4, lo32(acc[pp][2]), hi32(acc[pp][2]),
                            lo32(acc[pp][3]), hi32(acc[pp][3]));
            }
        }
    }
}

// ---------------------------------------------------------------------------
extern "C" void kernel_launch(void* const* d_in, const int* in_sizes, int n_in,
                              void* d_out, int out_size) {
    const float* feats  = (const float*)d_in[0];
    const float* W1     = (const float*)d_in[1];
    const float* b1     = (const float*)d_in[2];
    const float* W2     = (const float*)d_in[3];
    const float* b2     = (const float*)d_in[4];
    const int*   coords = (const int*)d_in[5];
    int M = in_sizes[0] / NCH;
    float* out = (float*)d_out;

    const int smem = (4096 + NCH * 128) * (int)sizeof(float);  // 49152 B

    int vq = (DG * DG * DG) / 4;
    k_fill<<<(vq + 255) / 256, 256>>>(vq);
    k_scatter<<<(M + 255) / 256, 256>>>(coords, M);
    k_pairs<<<(M + 255) / 256, 256>>>(coords, M);
    k_tilesbuild<<<1, 256>>>();

    int ptiles = (M + 127) / 128;
    const int OFFGRID = 592;    // ~4 blocks/SM * 148 SMs

    // Layer 1: g_h = b1 + feats@W1_center, then += 26 neighbor taps
    k_center<false><<<ptiles, 128, smem>>>(feats, W1 + CENTER * NCH * NCH, b1, g_h, M);
    k_off<false><<<OFFGRID, 128, smem>>>(feats, W1, g_h);

    // Layer 2 (gathers apply ReLU to g_h): out = b2 + relu(g_h)@W2_center + taps
    k_center<true><<<ptiles, 128, smem>>>(g_h, W2 + CENTER * NCH * NCH, b2, out, M);
    k_off<true><<<OFFGRID, 128, smem>>>(g_h, W2, out);

    int Mq = M * (NCH / 4);
    k_relu4<<<(Mq + 255) / 256, 256>>>((float4*)out, Mq);
}

// round 14
// speedup vs baseline: 7.4028x; 7.4028x over previous
#include <cuda_runtime.h>
#include <cuda_bf16.h>
#include <cstdint>

// Sparse 3x3x3 conv block, 2 layers, N=64, D=128.
// Center tap (offset 13) computed densely (no gather list, no atomics, bias
// fused, STG stores). 26 neighbor taps via compacted tile table + persistent
// strided blocks, FFMA2 (fma.rn.f32x2) inner loop, red.global.add.v4.f32
// scatter. Layer-1 ReLU fused into layer-2 gathers.
// CRITICAL: g_h is NEVER passed from host code (host shadow symbol + GB300
// ATS silently routes traffic to host memory, 7x regression in R8/R9).
// Kernels take nullptr sentinels and substitute the device symbol.
// NOTE: center must stay a separate launch from k_off — offset REDs must not
// race the center STG row-init (no inter-block ordering within a kernel).

#define DG   128
#define NCH  64
#define MAXM 131072
#define NOFF 27
#define CENTER 13
#define MAXTILES (26 * 1024 + 64)

__device__ __align__(16) int   g_lookup[DG * DG * DG];
__device__ __align__(16) int   g_cnt[NOFF];
__device__ __align__(16) int   g_pout[NOFF * MAXM];
__device__ __align__(16) int   g_pin [NOFF * MAXM];
__device__ __align__(16) float g_h   [MAXM * NCH];
__device__ __align__(16) int   g_tiletab[MAXTILES];
__device__ int g_ntiles;

// ---------------------------------------------------------------------------
__global__ void k_fill(int nquad) {
    int i = blockIdx.x * blockDim.x + threadIdx.x;
    if (i < nquad) ((int4*)g_lookup)[i] = make_int4(-1, -1, -1, -1);
    if (i < NOFF)  g_cnt[i] = 0;
}

__global__ void k_scatter(const int* __restrict__ coords, int M) {
    int i = blockIdx.x * blockDim.x + threadIdx.x;
    if (i >= M) return;
    int x = coords[3 * i + 0];
    int y = coords[3 * i + 1];
    int z = coords[3 * i + 2];
    g_lookup[(x * DG + y) * DG + z] = i;
}

// Pair lists for the 26 non-center offsets (warp-aggregated append).
__global__ void k_pairs(const int* __restrict__ coords, int M) {
    int i    = blockIdx.x * blockDim.x + threadIdx.x;
    int lane = threadIdx.x & 31;
    bool act = (i < M) && (i < MAXM);
    int cx = 0, cy = 0, cz = 0;
    if (act) {
        cx = coords[3 * i + 0];
        cy = coords[3 * i + 1];
        cz = coords[3 * i + 2];
    }
    for (int k = 0; k < NOFF; k++) {
        if (k == CENTER) continue;
        int dx = k / 9 - 1, dy = (k / 3) % 3 - 1, dz = k % 3 - 1;
        int nidx = -1;
        if (act) {
            int nx = cx + dx, ny = cy + dy, nz = cz + dz;
            if (nx >= 0 && nx < DG && ny >= 0 && ny < DG && nz >= 0 && nz < DG)
                nidx = g_lookup[(nx * DG + ny) * DG + nz];
        }
        bool valid = (nidx >= 0);
        unsigned m = __ballot_sync(0xffffffffu, valid);
        if (!m) continue;
        int total  = __popc(m);
        int leader = __ffs(m) - 1;
        int base = 0;
        if (lane == leader) base = atomicAdd(&g_cnt[k], total);
        base = __shfl_sync(0xffffffffu, base, leader);
        if (valid) {
            int pos = k * MAXM + base + __popc(m & ((1u << lane) - 1));
            g_pout[pos] = i;
            g_pin [pos] = nidx;
        }
    }
}

// Compact (offset, tile) descriptors: desc = (k<<16)|t. One block.
__global__ void k_tilesbuild() {
    __shared__ int pref[NOFF];
    int tid = threadIdx.x;
    if (tid == 0) {
        int s = 0;
        for (int k = 0; k < NOFF; k++) {
            pref[k] = s;
            if (k != CENTER) s += (g_cnt[k] + 127) / 128;
        }
        g_ntiles = s;
    }
    __syncthreads();
    for (int k = 0; k < NOFF; k++) {
        if (k == CENTER) continue;
        int nt = (g_cnt[k] + 127) / 128;
        for (int t = tid; t < nt; t += blockDim.x)
            g_tiletab[pref[k] + t] = (k << 16) | t;
    }
}

__global__ void k_relu4(float4* __restrict__ x, int nquad) {
    int i = blockIdx.x * blockDim.x + threadIdx.x;
    if (i < nquad) {
        float4 v = x[i];
        v.x = fmaxf(v.x, 0.f); v.y = fmaxf(v.y, 0.f);
        v.z = fmaxf(v.z, 0.f); v.w = fmaxf(v.w, 0.f);
        x[i] = v;
    }
}

// ---------------------------------------------------------------------------
__device__ __forceinline__ void fma2(unsigned long long& d,
                                     unsigned long long a,
                                     unsigned long long b) {
    asm("fma.rn.f32x2 %0, %1, %2, %3;" : "=l"(d) : "l"(a), "l"(b), "l"(d));
}
__device__ __forceinline__ unsigned long long dup2(float s) {
    unsigned long long d;
    unsigned u = __float_as_uint(s);
    asm("mov.b64 %0, {%1, %1};" : "=l"(d) : "r"(u));
    return d;
}
__device__ __forceinline__ float lo32(unsigned long long v) {
    return __uint_as_float((unsigned)v);
}
__device__ __forceinline__ float hi32(unsigned long long v) {
    return __uint_as_float((unsigned)(v >> 32));
}
__device__ __forceinline__ void red4(float* p, float a, float b, float c, float d) {
    asm volatile("red.global.add.v4.f32 [%0], {%1, %2, %3, %4};"
                 :: "l"(p), "f"(a), "f"(b), "f"(c), "f"(d) : "memory");
}

// Shared FFMA2 mainloop over sGT[j][p] x sW[j][c]: 8 points x 8 channels
// (4 packed channel-pairs) per thread.
__device__ __forceinline__ void gemm_tile(const float* sGT, const float* sW,
                                          int pg, int cg,
                                          unsigned long long (&acc)[8][4]) {
#pragma unroll
    for (int a = 0; a < 8; a++)
#pragma unroll
        for (int b = 0; b < 4; b++) acc[a][b] = 0ull;
    const float* gtb = sGT + pg * 8;
    const float* wb  = sW  + cg * 8;
#pragma unroll 4
    for (int j = 0; j < NCH; j++) {
        float4 a0 = *(const float4*)(gtb + j * 128);
        float4 a1 = *(const float4*)(gtb + j * 128 + 4);
        unsigned long long av[8];
        av[0] = dup2(a0.x); av[1] = dup2(a0.y);
        av[2] = dup2(a0.z); av[3] = dup2(a0.w);
        av[4] = dup2(a1.x); av[5] = dup2(a1.y);
        av[6] = dup2(a1.z); av[7] = dup2(a1.w);
        ulonglong2 b01 = *(const ulonglong2*)(wb + j * 64);
        ulonglong2 b23 = *(const ulonglong2*)(wb + j * 64 + 4);
        unsigned long long bv[4] = {b01.x, b01.y, b23.x, b23.y};
#pragma unroll
        for (int pp = 0; pp < 8; pp++)
#pragma unroll
            for (int c2 = 0; c2 < 4; c2++)
                fma2(acc[pp][c2], av[pp], bv[c2]);
    }
}

// Center tap: out[i] = bias + x[i] @ Wc, dense over points, STG stores.
// xin==nullptr -> g_h; outp==nullptr -> g_h.
template<bool RELU>
__global__ void __launch_bounds__(128) k_center(const float* xin,
                                                const float* __restrict__ Wc,
                                                const float* __restrict__ bias,
                                                float* outp, int M) {
    extern __shared__ float sm[];
    float* sW  = sm;
    float* sGT = sm + 4096;

    const float* x = xin  ? xin  : (const float*)g_h;
    float* out     = outp ? outp : g_h;

    int base = blockIdx.x * 128;
    int tx = threadIdx.x;

    const float4* Wk4 = (const float4*)Wc;
    float4* sW4 = (float4*)sW;
#pragma unroll
    for (int t = 0; t < 8; t++) sW4[tx + t * 128] = Wk4[tx + t * 128];

    int p = tx;
    int row = base + p;
    if (row < M) {
        const float4* r4 = (const float4*)(x + (size_t)row * NCH);
#pragma unroll
        for (int q = 0; q < 16; q++) {
            float4 v = r4[q];
            if (RELU) {
                v.x = fmaxf(v.x, 0.f); v.y = fmaxf(v.y, 0.f);
                v.z = fmaxf(v.z, 0.f); v.w = fmaxf(v.w, 0.f);
            }
            sGT[(4 * q + 0) * 128 + p] = v.x;
            sGT[(4 * q + 1) * 128 + p] = v.y;
            sGT[(4 * q + 2) * 128 + p] = v.z;
            sGT[(4 * q + 3) * 128 + p] = v.w;
        }
    } else {
#pragma unroll
        for (int j = 0; j < NCH; j++) sGT[j * 128 + p] = 0.0f;
    }
    __syncthreads();

    int cg = tx & 7, pg = tx >> 3;
    unsigned long long acc[8][4];
    gemm_tile(sGT, sW, pg, cg, acc);

    float4 bA = *(const float4*)(bias + cg * 8);
    float4 bB = *(const float4*)(bias + cg * 8 + 4);
#pragma unroll
    for (int pp = 0; pp < 8; pp++) {
        int r = base + pg * 8 + pp;
        if (r < M) {
            float* o = out + (size_t)r * NCH + cg * 8;
            float4 v0 = make_float4(lo32(acc[pp][0]) + bA.x, hi32(acc[pp][0]) + bA.y,
                                    lo32(acc[pp][1]) + bA.z, hi32(acc[pp][1]) + bA.w);
            float4 v1 = make_float4(lo32(acc[pp][2]) + bB.x, hi32(acc[pp][2]) + bB.y,
                                    lo32(acc[pp][3]) + bB.z, hi32(acc[pp][3]) + bB.w);
            *(float4*)o = v0;
            *(float4*)(o + 4) = v1;
        }
    }
}

// 26 neighbor taps: persistent blocks stride over the compact tile table.
// xin==nullptr -> g_h; outp==nullptr -> g_h.
template<bool RELU>
__global__ void __launch_bounds__(128) k_off(const float* xin,
                                             const float* __restrict__ W,
                                             float* outp) {
    extern __shared__ float sm[];
    float* sW  = sm;
    float* sGT = sm + 4096;

    const float* x = xin  ? xin  : (const float*)g_h;
    float* out     = outp ? outp : g_h;

    int tx = threadIdx.x;
    int ntiles = g_ntiles;

    for (int ti = blockIdx.x; ti < ntiles; ti += gridDim.x) {
        __syncthreads();   // protect smem from previous iteration's readers
        int desc = g_tiletab[ti];
        int k    = desc >> 16;
        int base = (desc & 0xffff) * 128;
        int cnt  = g_cnt[k];

        const float4* Wk4 = (const float4*)(W + k * (NCH * NCH));
        float4* sW4 = (float4*)sW;
#pragma unroll
        for (int t = 0; t < 8; t++) sW4[tx + t * 128] = Wk4[tx + t * 128];

        int p = tx;
        if (base + p < cnt) {
            int gidx = g_pin[k * MAXM + base + p];
            const float4* r4 = (const float4*)(x + (size_t)gidx * NCH);
#pragma unroll
            for (int q = 0; q < 16; q++) {
                float4 v = r4[q];
                if (RELU) {
                    v.x = fmaxf(v.x, 0.f); v.y = fmaxf(v.y, 0.f);
                    v.z = fmaxf(v.z, 0.f); v.w = fmaxf(v.w, 0.f);
                }
                sGT[(4 * q + 0) * 128 + p] = v.x;
                sGT[(4 * q + 1) * 128 + p] = v.y;
                sGT[(4 * q + 2) * 128 + p] = v.z;
                sGT[(4 * q + 3) * 128 + p] = v.w;
            }
        } else {
#pragma unroll
            for (int j = 0; j < NCH; j++) sGT[j * 128 + p] = 0.0f;
        }
        __syncthreads();

        int cg = tx & 7, pg = tx >> 3;
        unsigned long long acc[8][4];
        gemm_tile(sGT, sW, pg, cg, acc);

#pragma unroll
        for (int pp = 0; pp < 8; pp++) {
            int pairidx = base + pg * 8 + pp;
            if (pairidx < cnt) {
                int row = g_pout[k * MAXM + pairidx];
                float* o = out + (size_t)row * NCH + cg * 8;
                red4(o,     lo32(acc[pp][0]), hi32(acc[pp][0]),
                            lo32(acc[pp][1]), hi32(acc[pp][1]));
                red4(o + 4, lo32(acc[pp][2]), hi32(acc[pp][2]),
                            lo32(acc[pp][3]), hi32(acc[pp][3]));
            }
        }
    }
}

// ---------------------------------------------------------------------------
extern "C" void kernel_launch(void* const* d_in, const int* in_sizes, int n_in,
                              void* d_out, int out_size) {
    const float* feats  = (const float*)d_in[0];
    const float* W1     = (const float*)d_in[1];
    const float* b1     = (const float*)d_in[2];
    const float* W2     = (const float*)d_in[3];
    const float* b2     = (const float*)d_in[4];
    const int*   coords = (const int*)d_in[5];
    int M = in_sizes[0] / NCH;
    float* out = (float*)d_out;

    const int smem = (4096 + NCH * 128) * (int)sizeof(float);  // 49152 B

    int vq = (DG * DG * DG) / 4;
    k_fill<<<(vq + 255) / 256, 256>>>(vq);
    k_scatter<<<(M + 255) / 256, 256>>>(coords, M);
    k_pairs<<<(M + 255) / 256, 256>>>(coords, M);
    k_tilesbuild<<<1, 256>>>();

    int ptiles = (M + 127) / 128;
    const int OFFGRID = 592;    // ~4 blocks/SM * 148 SMs

    // Layer 1: g_h = b1 + feats@W1_center, then += 26 neighbor taps
    // (g_h referenced ONLY via in-kernel device symbol; nullptr sentinel here)
    k_center<false><<<ptiles, 128, smem>>>(feats, W1 + CENTER * NCH * NCH, b1, nullptr, M);
    k_off<false><<<OFFGRID, 128, smem>>>(feats, W1, nullptr);

    // Layer 2 (gathers apply ReLU to g_h): out = b2 + relu(g_h)@W2_center + taps
    k_center<true><<<ptiles, 128, smem>>>(nullptr, W2 + CENTER * NCH * NCH, b2, out, M);
    k_off<true><<<OFFGRID, 128, smem>>>(nullptr, W2, out);

    int Mq = M * (NCH / 4);
    k_relu4<<<(Mq + 255) / 256, 256>>>((float4*)out, Mq);
}

// round 15
// speedup vs baseline: 9.2420x; 1.2484x over previous
#include <cuda_runtime.h>
#include <cuda_bf16.h>
#include <cstdint>

// Sparse 3x3x3 conv block, 2 layers, N=64, D=128.
// Center tap dense (STG, bias fused); 26 neighbor taps via compact tile table
// (per-tile count packed in descriptor) + persistent blocks; FFMA2 mainloop;
// red.global.add.v4.f32 scatter; ReLU fused into layer-2 gathers.
// CRITICAL: g_h NEVER passed from host (GB300 ATS host-shadow trap, R8/R9).
// Pair build: pipelined 27 lookups, block-aggregated counts, 1 atomic per
// block per offset (issued concurrently across 27 addresses).

#define DG   128
#define NCH  64
#define MAXM 131072
#define NOFF 27
#define CENTER 13
#define MAXTILES (26 * 1024 + 64)

__device__ __align__(16) int   g_lookup[DG * DG * DG];
__device__ __align__(16) int   g_cnt[NOFF];
__device__ __align__(16) int   g_pout[NOFF * MAXM];
__device__ __align__(16) int   g_pin [NOFF * MAXM];
__device__ __align__(16) float g_h   [MAXM * NCH];
__device__ __align__(16) int   g_tiletab[MAXTILES];
__device__ int g_ntiles;

// ---------------------------------------------------------------------------
__global__ void k_fill(int nquad) {
    int i = blockIdx.x * blockDim.x + threadIdx.x;
    if (i < nquad) ((int4*)g_lookup)[i] = make_int4(-1, -1, -1, -1);
    if (i < NOFF)  g_cnt[i] = 0;
    if (i == 0)    g_ntiles = 0;
}

__global__ void k_scatter(const int* __restrict__ coords, int M) {
    int i = blockIdx.x * blockDim.x + threadIdx.x;
    if (i >= M) return;
    int x = coords[3 * i + 0];
    int y = coords[3 * i + 1];
    int z = coords[3 * i + 2];
    g_lookup[(x * DG + y) * DG + z] = i;
}

// Pair lists for 26 non-center offsets. 256 threads/block.
// Phase 1: all 27 neighbor lookups as independent (pipelined) LDGs.
// Then block-aggregated counts -> 1 atomic per block per offset, issued
// concurrently by 27 threads. Phase 2: indexed writes.
__global__ void __launch_bounds__(256) k_pairs(const int* __restrict__ coords, int M) {
    __shared__ int swpre[NOFF][8];   // per-warp exclusive prefix within block
    __shared__ int sbase[NOFF];      // global base per offset for this block
    int tid  = threadIdx.x;
    int lane = tid & 31;
    int wid  = tid >> 5;
    int i    = blockIdx.x * 256 + tid;
    bool act = (i < M) && (i < MAXM);
    int cx = 0, cy = 0, cz = 0;
    if (act) {
        cx = coords[3 * i + 0];
        cy = coords[3 * i + 1];
        cz = coords[3 * i + 2];
    }
    int nidx[NOFF];
#pragma unroll
    for (int k = 0; k < NOFF; k++) {
        nidx[k] = -1;
        if (k == CENTER) continue;
        int dx = k / 9 - 1, dy = (k / 3) % 3 - 1, dz = k % 3 - 1;
        if (act) {
            int nx = cx + dx, ny = cy + dy, nz = cz + dz;
            if (nx >= 0 && nx < DG && ny >= 0 && ny < DG && nz >= 0 && nz < DG)
                nidx[k] = g_lookup[(nx * DG + ny) * DG + nz];
        }
    }
#pragma unroll
    for (int k = 0; k < NOFF; k++) {
        if (k == CENTER) continue;
        unsigned m = __ballot_sync(0xffffffffu, nidx[k] >= 0);
        if (lane == 0) swpre[k][wid] = __popc(m);
    }
    __syncthreads();
    if (tid < NOFF && tid != CENTER) {
        int s = 0;
#pragma unroll
        for (int w = 0; w < 8; w++) { int t = swpre[tid][w]; swpre[tid][w] = s; s += t; }
        sbase[tid] = s ? atomicAdd(&g_cnt[tid], s) : 0;
    }
    __syncthreads();
#pragma unroll
    for (int k = 0; k < NOFF; k++) {
        if (k == CENTER) continue;
        unsigned m = __ballot_sync(0xffffffffu, nidx[k] >= 0);
        if (nidx[k] >= 0) {
            int pos = k * MAXM + sbase[k] + swpre[k][wid] + __popc(m & ((1u << lane) - 1));
            g_pout[pos] = i;
            g_pin [pos] = nidx[k];
        }
    }
}

// Parallel tile-table build: one block per offset, range reserved atomically.
// Descriptor packs k (5b), tile index t (11b), per-tile count ctile (8b):
// desc = (k<<19) | (t<<8) | ctile  -> k_off needs NO g_cnt load.
__global__ void k_tilesbuild() {
    int k = blockIdx.x;
    if (k == CENTER) return;
    int cnt = g_cnt[k];
    int nt  = (cnt + 127) / 128;
    __shared__ int base;
    if (threadIdx.x == 0) base = nt ? atomicAdd(&g_ntiles, nt) : 0;
    __syncthreads();
    for (int t = threadIdx.x; t < nt; t += blockDim.x) {
        int ctile = cnt - t * 128;
        if (ctile > 128) ctile = 128;
        g_tiletab[base + t] = (k << 19) | (t << 8) | ctile;
    }
}

__global__ void k_relu4(float4* __restrict__ x, int nquad) {
    int i = blockIdx.x * blockDim.x + threadIdx.x;
    if (i < nquad) {
        float4 v = x[i];
        v.x = fmaxf(v.x, 0.f); v.y = fmaxf(v.y, 0.f);
        v.z = fmaxf(v.z, 0.f); v.w = fmaxf(v.w, 0.f);
        x[i] = v;
    }
}

// ---------------------------------------------------------------------------
__device__ __forceinline__ void fma2(unsigned long long& d,
                                     unsigned long long a,
                                     unsigned long long b) {
    asm("fma.rn.f32x2 %0, %1, %2, %3;" : "=l"(d) : "l"(a), "l"(b), "l"(d));
}
__device__ __forceinline__ unsigned long long dup2(float s) {
    unsigned long long d;
    unsigned u = __float_as_uint(s);
    asm("mov.b64 %0, {%1, %1};" : "=l"(d) : "r"(u));
    return d;
}
__device__ __forceinline__ float lo32(unsigned long long v) {
    return __uint_as_float((unsigned)v);
}
__device__ __forceinline__ float hi32(unsigned long long v) {
    return __uint_as_float((unsigned)(v >> 32));
}
__device__ __forceinline__ void red4(float* p, float a, float b, float c, float d) {
    asm volatile("red.global.add.v4.f32 [%0], {%1, %2, %3, %4};"
                 :: "l"(p), "f"(a), "f"(b), "f"(c), "f"(d) : "memory");
}

// FFMA2 mainloop over sGT[j][p] x sW[j][c]: 8 points x 8 channels per thread.
__device__ __forceinline__ void gemm_tile(const float* sGT, const float* sW,
                                          int pg, int cg,
                                          unsigned long long (&acc)[8][4]) {
#pragma unroll
    for (int a = 0; a < 8; a++)
#pragma unroll
        for (int b = 0; b < 4; b++) acc[a][b] = 0ull;
    const float* gtb = sGT + pg * 8;
    const float* wb  = sW  + cg * 8;
#pragma unroll 4
    for (int j = 0; j < NCH; j++) {
        float4 a0 = *(const float4*)(gtb + j * 128);
        float4 a1 = *(const float4*)(gtb + j * 128 + 4);
        unsigned long long av[8];
        av[0] = dup2(a0.x); av[1] = dup2(a0.y);
        av[2] = dup2(a0.z); av[3] = dup2(a0.w);
        av[4] = dup2(a1.x); av[5] = dup2(a1.y);
        av[6] = dup2(a1.z); av[7] = dup2(a1.w);
        ulonglong2 b01 = *(const ulonglong2*)(wb + j * 64);
        ulonglong2 b23 = *(const ulonglong2*)(wb + j * 64 + 4);
        unsigned long long bv[4] = {b01.x, b01.y, b23.x, b23.y};
#pragma unroll
        for (int pp = 0; pp < 8; pp++)
#pragma unroll
            for (int c2 = 0; c2 < 4; c2++)
                fma2(acc[pp][c2], av[pp], bv[c2]);
    }
}

// Center tap: out[i] = bias + x[i] @ Wc. Persistent-strided; W staged once.
// xin==nullptr -> g_h; outp==nullptr -> g_h.
template<bool RELU>
__global__ void __launch_bounds__(128) k_center(const float* xin,
                                                const float* __restrict__ Wc,
                                                const float* __restrict__ bias,
                                                float* outp, int M) {
    extern __shared__ float sm[];
    float* sW  = sm;
    float* sGT = sm + 4096;

    const float* x = xin  ? xin  : (const float*)g_h;
    float* out     = outp ? outp : g_h;

    int tx = threadIdx.x;
    int cg = tx & 7, pg = tx >> 3;

    const float4* Wk4 = (const float4*)Wc;
    float4* sW4 = (float4*)sW;
#pragma unroll
    for (int t = 0; t < 8; t++) sW4[tx + t * 128] = Wk4[tx + t * 128];

    float4 bA = *(const float4*)(bias + cg * 8);
    float4 bB = *(const float4*)(bias + cg * 8 + 4);

    for (int base = blockIdx.x * 128; base < M; base += gridDim.x * 128) {
        __syncthreads();           // sW visible (1st iter); sGT reuse (later)
        int row = base + tx;
        if (row < M) {
            const float4* r4 = (const float4*)(x + (size_t)row * NCH);
#pragma unroll
            for (int q = 0; q < 16; q++) {
                float4 v = r4[q];
                if (RELU) {
                    v.x = fmaxf(v.x, 0.f); v.y = fmaxf(v.y, 0.f);
                    v.z = fmaxf(v.z, 0.f); v.w = fmaxf(v.w, 0.f);
                }
                sGT[(4 * q + 0) * 128 + tx] = v.x;
                sGT[(4 * q + 1) * 128 + tx] = v.y;
                sGT[(4 * q + 2) * 128 + tx] = v.z;
                sGT[(4 * q + 3) * 128 + tx] = v.w;
            }
        } else {
#pragma unroll
            for (int j = 0; j < NCH; j++) sGT[j * 128 + tx] = 0.0f;
        }
        __syncthreads();

        unsigned long long acc[8][4];
        gemm_tile(sGT, sW, pg, cg, acc);

#pragma unroll
        for (int pp = 0; pp < 8; pp++) {
            int r = base + pg * 8 + pp;
            if (r < M) {
                float* o = out + (size_t)r * NCH + cg * 8;
                float4 v0 = make_float4(lo32(acc[pp][0]) + bA.x, hi32(acc[pp][0]) + bA.y,
                                        lo32(acc[pp][1]) + bA.z, hi32(acc[pp][1]) + bA.w);
                float4 v1 = make_float4(lo32(acc[pp][2]) + bB.x, hi32(acc[pp][2]) + bB.y,
                                        lo32(acc[pp][3]) + bB.z, hi32(acc[pp][3]) + bB.w);
                *(float4*)o = v0;
                *(float4*)(o + 4) = v1;
            }
        }
    }
}

// 26 neighbor taps: persistent blocks stride over the compact tile table.
// xin==nullptr -> g_h; outp==nullptr -> g_h.
template<bool RELU>
__global__ void __launch_bounds__(128) k_off(const float* xin,
                                             const float* __restrict__ W,
                                             float* outp) {
    extern __shared__ float sm[];
    float* sW  = sm;
    float* sGT = sm + 4096;

    const float* x = xin  ? xin  : (const float*)g_h;
    float* out     = outp ? outp : g_h;

    int tx = threadIdx.x;
    int cg = tx & 7, pg = tx >> 3;
    int ntiles = g_ntiles;

    for (int ti = blockIdx.x; ti < ntiles; ti += gridDim.x) {
        __syncthreads();   // protect smem from previous iteration's readers
        int desc  = g_tiletab[ti];
        int k     = desc >> 19;
        int base  = ((desc >> 8) & 0x7FF) * 128;
        int ctile = desc & 0xFF;            // pairs in this tile (1..128)

        const float4* Wk4 = (const float4*)(W + k * (NCH * NCH));
        float4* sW4 = (float4*)sW;
#pragma unroll
        for (int t = 0; t < 8; t++) sW4[tx + t * 128] = Wk4[tx + t * 128];

        if (tx < ctile) {
            int gidx = g_pin[k * MAXM + base + tx];
            const float4* r4 = (const float4*)(x + (size_t)gidx * NCH);
#pragma unroll
            for (int q = 0; q < 16; q++) {
                float4 v = r4[q];
                if (RELU) {
                    v.x = fmaxf(v.x, 0.f); v.y = fmaxf(v.y, 0.f);
                    v.z = fmaxf(v.z, 0.f); v.w = fmaxf(v.w, 0.f);
                }
                sGT[(4 * q + 0) * 128 + tx] = v.x;
                sGT[(4 * q + 1) * 128 + tx] = v.y;
                sGT[(4 * q + 2) * 128 + tx] = v.z;
                sGT[(4 * q + 3) * 128 + tx] = v.w;
            }
        } else {
#pragma unroll
            for (int j = 0; j < NCH; j++) sGT[j * 128 + tx] = 0.0f;
        }
        __syncthreads();

        unsigned long long acc[8][4];
        gemm_tile(sGT, sW, pg, cg, acc);

#pragma unroll
        for (int pp = 0; pp < 8; pp++) {
            int pl = pg * 8 + pp;
            if (pl < ctile) {
                int row = g_pout[k * MAXM + base + pl];
                float* o = out + (size_t)row * NCH + cg * 8;
                red4(o,     lo32(acc[pp][0]), hi32(acc[pp][0]),
                            lo32(acc[pp][1]), hi32(acc[pp][1]));
                red4(o + 4, lo32(acc[pp][2]), hi32(acc[pp][2]),
                            lo32(acc[pp][3]), hi32(acc[pp][3]));
            }
        }
    }
}

// ---------------------------------------------------------------------------
extern "C" void kernel_launch(void* const* d_in, const int* in_sizes, int n_in,
                              void* d_out, int out_size) {
    const float* feats  = (const float*)d_in[0];
    const float* W1     = (const float*)d_in[1];
    const float* b1     = (const float*)d_in[2];
    const float* W2     = (const float*)d_in[3];
    const float* b2     = (const float*)d_in[4];
    const int*   coords = (const int*)d_in[5];
    int M = in_sizes[0] / NCH;
    float* out = (float*)d_out;

    const int smem = (4096 + NCH * 128) * (int)sizeof(float);  // 49152 B

    int vq = (DG * DG * DG) / 4;
    k_fill<<<(vq + 255) / 256, 256>>>(vq);
    k_scatter<<<(M + 255) / 256, 256>>>(coords, M);
    k_pairs<<<(M + 255) / 256, 256>>>(coords, M);
    k_tilesbuild<<<NOFF, 128>>>();

    const int GRID = 592;    // ~4 blocks/SM * 148 SMs

    // Layer 1: g_h = b1 + feats@W1_center, then += 26 neighbor taps
    // (g_h referenced ONLY via in-kernel device symbol; nullptr sentinel)
    k_center<false><<<GRID, 128, smem>>>(feats, W1 + CENTER * NCH * NCH, b1, nullptr, M);
    k_off<false><<<GRID, 128, smem>>>(feats, W1, nullptr);

    // Layer 2 (gathers apply ReLU to g_h): out = b2 + relu(g_h)@W2_center + taps
    k_center<true><<<GRID, 128, smem>>>(nullptr, W2 + CENTER * NCH * NCH, b2, out, M);
    k_off<true><<<GRID, 128, smem>>>(nullptr, W2, out);

    int Mq = M * (NCH / 4);
    k_relu4<<<(Mq + 255) / 256, 256>>>((float4*)out, Mq);
}